// round 11
// baseline (speedup 1.0000x reference)
#include <cuda_runtime.h>

// y[tok][o] = sum_e cos(x[tok][e] + theta[e]) * W[o][e],  E = 16, ntok = 1,048,576
//
// Warp handles 8 tokens/step (quad q owns token q; lane-slice i covers
// components/outputs [4i..4i+4)). Coalesced 512B warp loads/stores. W in
// registers (butterfly-permuted). z exchanged as packed f32x2 pairs via
// shfl.xor. Two-level load pipeline:
//   * register prefetch: next group (g+nwarps) loaded into regs during compute
//   * L2 prefetch:       group after next (g+2*nwarps) warmed via prefetch.global.L2
// so the in-body prefetch LDG sees L2 latency (~250cyc, hidden by the 4-octet
// body) and the consume sees zero.

#define BLK 128
#define U   4
#define WPB (BLK / 32)

__device__ __forceinline__ unsigned long long pack2(float a, float b) {
    unsigned long long r;
    asm("mov.b64 %0, {%1, %2};" : "=l"(r) : "f"(a), "f"(b));
    return r;
}
__device__ __forceinline__ void unpack2(unsigned long long v, float& a, float& b) {
    asm("mov.b64 {%0, %1}, %2;" : "=f"(a), "=f"(b) : "l"(v));
}
__device__ __forceinline__ unsigned long long ffma2(unsigned long long a,
                                                    unsigned long long b,
                                                    unsigned long long c) {
    unsigned long long d;
    asm("fma.rn.f32x2 %0, %1, %2, %3;" : "=l"(d) : "l"(a), "l"(b), "l"(c));
    return d;
}
__device__ __forceinline__ unsigned long long fmul2(unsigned long long a,
                                                    unsigned long long b) {
    unsigned long long d;
    asm("mul.rn.f32x2 %0, %1, %2;" : "=l"(d) : "l"(a), "l"(b));
    return d;
}
__device__ __forceinline__ unsigned long long shflx64(unsigned long long v, int m) {
    return __shfl_xor_sync(0xFFFFFFFFu, v, m, 4);
}
__device__ __forceinline__ void prefetch_l2(const void* p) {
    asm volatile("prefetch.global.L2 [%0];" :: "l"(p));
}

__global__ __launch_bounds__(BLK, 4)
void qmha_kernel(const float4* __restrict__ x4,
                 const float* __restrict__ theta,
                 const float* __restrict__ w,      // [16][16] row-major w[o][e]
                 float4* __restrict__ out4,
                 int ntok)
{
    __shared__ float sW[256];

    const int tid  = threadIdx.x;
    const int lane = tid & 31;
    const int i    = lane & 3;    // slice within quad
    const int q    = lane >> 2;   // token within octet

    sW[tid * 2 + 0] = w[tid * 2 + 0];
    sW[tid * 2 + 1] = w[tid * 2 + 1];
    __syncthreads();

    // W packed by e-pairs in butterfly arrival order:
    //   slot s holds e-block b = i ^ s; h selects pair {4b+2h, 4b+2h+1};
    //   Wc[s][h][r] = { W[4i+r][4b+2h], W[4i+r][4b+2h+1] }
    unsigned long long Wc[4][2][4];
#pragma unroll
    for (int s = 0; s < 4; s++) {
        const int b = i ^ s;
#pragma unroll
        for (int h = 0; h < 2; h++) {
            const int e0 = 4 * b + 2 * h;
#pragma unroll
            for (int r = 0; r < 4; r++)
                Wc[s][h][r] = pack2(sW[(4 * i + r) * 16 + e0],
                                    sW[(4 * i + r) * 16 + e0 + 1]);
        }
    }
    const float4 th = reinterpret_cast<const float4*>(theta)[i];

    const int warp_id = blockIdx.x * WPB + (tid >> 5);
    const int nwarps  = gridDim.x * WPB;
    const int noct    = (ntok + 7) >> 3;
    const int ngrp    = (noct + U - 1) / U;

    // ---- prologue: load group g0 into regs, warm L2 for g0+nwarps ----
    int g = warp_id;
    float4 xv[U];
    if (g < ngrp) {
        const int oct0 = g * U;
        const bool full = (oct0 * 8 + U * 8) <= ntok;
#pragma unroll
        for (int u = 0; u < U; u++) {
            const int tok = (oct0 + u) * 8 + q;
            xv[u] = (full || tok < ntok)
                      ? __ldcs(&x4[(size_t)(oct0 + u) * 32 + lane])
                      : make_float4(0.f, 0.f, 0.f, 0.f);
        }
        const int g1 = g + nwarps;
        if (g1 < ngrp) {
            const int oct1 = g1 * U;
#pragma unroll
            for (int u = 0; u < U; u++)
                prefetch_l2(&x4[(size_t)(oct1 + u) * 32 + lane]);
        }
    }

    for (; g < ngrp; ) {
        const int gn = g + nwarps;

        // ---- L2-prefetch group g+2 (consumed by the reg-prefetch next iter)
        const int g2 = gn + nwarps;
        if (g2 < ngrp) {
            const int oct2 = g2 * U;
#pragma unroll
            for (int u = 0; u < U; u++)
                prefetch_l2(&x4[(size_t)(oct2 + u) * 32 + lane]);
        }

        // ---- register-prefetch group g+1 (should hit warm L2)
        float4 xn[U];
        if (gn < ngrp) {
            const int oct0n = gn * U;
            const bool fulln = (oct0n * 8 + U * 8) <= ntok;
#pragma unroll
            for (int u = 0; u < U; u++) {
                const int tok = (oct0n + u) * 8 + q;
                xn[u] = (fulln || tok < ntok)
                          ? __ldcs(&x4[(size_t)(oct0n + u) * 32 + lane])
                          : make_float4(0.f, 0.f, 0.f, 0.f);
            }
        }

        // ---- compute + store current group (data already in registers)
        const int oct0 = g * U;
        const bool full = (oct0 * 8 + U * 8) <= ntok;
#pragma unroll
        for (int u = 0; u < U; u++) {
            const unsigned long long p0 = pack2(__cosf(xv[u].x + th.x),
                                                __cosf(xv[u].y + th.y));
            const unsigned long long p1 = pack2(__cosf(xv[u].z + th.z),
                                                __cosf(xv[u].w + th.w));

            const unsigned long long q0 = shflx64(p0, 1);
            const unsigned long long q1 = shflx64(p1, 1);

            unsigned long long acc[4];
#pragma unroll
            for (int r = 0; r < 4; r++) {
                acc[r] = fmul2(p0, Wc[0][0][r]);
                acc[r] = ffma2(p1, Wc[0][1][r], acc[r]);
            }

            const unsigned long long r0 = shflx64(p0, 2);
            const unsigned long long r1 = shflx64(p1, 2);
#pragma unroll
            for (int r = 0; r < 4; r++) {
                acc[r] = ffma2(q0, Wc[1][0][r], acc[r]);
                acc[r] = ffma2(q1, Wc[1][1][r], acc[r]);
            }

            const unsigned long long s0 = shflx64(q0, 2);
            const unsigned long long s1 = shflx64(q1, 2);
#pragma unroll
            for (int r = 0; r < 4; r++) {
                acc[r] = ffma2(r0, Wc[2][0][r], acc[r]);
                acc[r] = ffma2(r1, Wc[2][1][r], acc[r]);
            }
#pragma unroll
            for (int r = 0; r < 4; r++) {
                acc[r] = ffma2(s0, Wc[3][0][r], acc[r]);
                acc[r] = ffma2(s1, Wc[3][1][r], acc[r]);
            }

            float4 yv;
            {
                float a, b;
                unpack2(acc[0], a, b); yv.x = a + b;
                unpack2(acc[1], a, b); yv.y = a + b;
                unpack2(acc[2], a, b); yv.z = a + b;
                unpack2(acc[3], a, b); yv.w = a + b;
            }

            if (full || ((oct0 + u) * 8 + q) < ntok)
                __stcs(&out4[(size_t)(oct0 + u) * 32 + lane], yv);
        }

        // ---- rotate buffers
        g = gn;
#pragma unroll
        for (int u = 0; u < U; u++) xv[u] = xn[u];
    }
}

extern "C" void kernel_launch(void* const* d_in, const int* in_sizes, int n_in,
                              void* d_out, int out_size) {
    const float* x     = (const float*)d_in[0];   // [B, S, 16] f32
    const float* theta = (const float*)d_in[1];   // [16] f32
    const float* w     = (const float*)d_in[2];   // [16, 16] f32
    float* out         = (float*)d_out;           // [B, S, 16] f32

    const int ntok = in_sizes[0] / 16;

    const int noct = (ntok + 7) >> 3;
    const int ngrp = (noct + U - 1) / U;
    int blocks = (ngrp + WPB - 1) / WPB;
    const int cap = 148 * 4;   // single resident wave at 4 blocks/SM
    if (blocks > cap) blocks = cap;

    qmha_kernel<<<blocks, BLK>>>((const float4*)x, theta, w, (float4*)out, ntok);
}

// round 13
// speedup vs baseline: 1.0667x; 1.0667x over previous
#include <cuda_runtime.h>

// y[tok][o] = sum_e cos(x[tok][e] + theta[e]) * W[o][e],  E = 16, ntok = 1,048,576
//
// cp.async 6-stage smem pipeline for the x stream (no register double-buffer,
// no exposed DRAM latency on the consume path). Per block (128 thr): stage =
// 64 tokens = 4KB; 2x cp.async.cg 16B per thread per stage; wait_group<S-2> +
// one __syncthreads per stage. Compute: warp handles 8-token octets (quad q
// owns token q, lane-slice i owns components/outputs [4i..4i+4)); W in
// registers (butterfly-permuted); z exchanged as packed f32x2 via shfl.xor.

#define BLK 128
#define S   6      // pipeline stages
#define GT  64     // tokens per stage
#define GF4 (GT * 4)   // float4 per stage (256) = 4KB

__device__ __forceinline__ unsigned long long pack2(float a, float b) {
    unsigned long long r;
    asm("mov.b64 %0, {%1, %2};" : "=l"(r) : "f"(a), "f"(b));
    return r;
}
__device__ __forceinline__ void unpack2(unsigned long long v, float& a, float& b) {
    asm("mov.b64 {%0, %1}, %2;" : "=f"(a), "=f"(b) : "l"(v));
}
__device__ __forceinline__ unsigned long long ffma2(unsigned long long a,
                                                    unsigned long long b,
                                                    unsigned long long c) {
    unsigned long long d;
    asm("fma.rn.f32x2 %0, %1, %2, %3;" : "=l"(d) : "l"(a), "l"(b), "l"(c));
    return d;
}
__device__ __forceinline__ unsigned long long fmul2(unsigned long long a,
                                                    unsigned long long b) {
    unsigned long long d;
    asm("mul.rn.f32x2 %0, %1, %2;" : "=l"(d) : "l"(a), "l"(b));
    return d;
}
__device__ __forceinline__ unsigned long long shflx64(unsigned long long v, int m) {
    return __shfl_xor_sync(0xFFFFFFFFu, v, m, 4);
}
__device__ __forceinline__ void cp16(float4* dst_smem, const float4* src) {
    unsigned int d = (unsigned int)__cvta_generic_to_shared(dst_smem);
    asm volatile("cp.async.cg.shared.global [%0], [%1], 16;"
                 :: "r"(d), "l"(src) : "memory");
}
__device__ __forceinline__ void cp_commit() {
    asm volatile("cp.async.commit_group;" ::: "memory");
}
template <int N>
__device__ __forceinline__ void cp_wait() {
    asm volatile("cp.async.wait_group %0;" :: "n"(N) : "memory");
}

// one 8-token octet: xv is this lane's float4 slice; returns this lane's y slice
__device__ __forceinline__ float4 compute_octet(
    float4 xv, float4 th, const unsigned long long (&Wc)[4][2][4])
{
    const unsigned long long p0 = pack2(__cosf(xv.x + th.x), __cosf(xv.y + th.y));
    const unsigned long long p1 = pack2(__cosf(xv.z + th.z), __cosf(xv.w + th.w));

    const unsigned long long q0 = shflx64(p0, 1);
    const unsigned long long q1 = shflx64(p1, 1);

    unsigned long long acc[4];
#pragma unroll
    for (int r = 0; r < 4; r++) {
        acc[r] = fmul2(p0, Wc[0][0][r]);
        acc[r] = ffma2(p1, Wc[0][1][r], acc[r]);
    }
    const unsigned long long r0 = shflx64(p0, 2);
    const unsigned long long r1 = shflx64(p1, 2);
#pragma unroll
    for (int r = 0; r < 4; r++) {
        acc[r] = ffma2(q0, Wc[1][0][r], acc[r]);
        acc[r] = ffma2(q1, Wc[1][1][r], acc[r]);
    }
    const unsigned long long s0 = shflx64(q0, 2);
    const unsigned long long s1 = shflx64(q1, 2);
#pragma unroll
    for (int r = 0; r < 4; r++) {
        acc[r] = ffma2(r0, Wc[2][0][r], acc[r]);
        acc[r] = ffma2(r1, Wc[2][1][r], acc[r]);
    }
#pragma unroll
    for (int r = 0; r < 4; r++) {
        acc[r] = ffma2(s0, Wc[3][0][r], acc[r]);
        acc[r] = ffma2(s1, Wc[3][1][r], acc[r]);
    }

    float4 yv;
    float a, b;
    unpack2(acc[0], a, b); yv.x = a + b;
    unpack2(acc[1], a, b); yv.y = a + b;
    unpack2(acc[2], a, b); yv.z = a + b;
    unpack2(acc[3], a, b); yv.w = a + b;
    return yv;
}

__global__ __launch_bounds__(BLK, 4)
void qmha_kernel(const float4* __restrict__ x4,
                 const float* __restrict__ theta,
                 const float* __restrict__ w,      // [16][16] row-major w[o][e]
                 float4* __restrict__ out4,
                 int ntok)
{
    __shared__ float sW[256];
    __shared__ __align__(16) float4 sx[S][GF4];   // 24KB ring

    const int tid  = threadIdx.x;
    const int lane = tid & 31;
    const int wid  = tid >> 5;
    const int i    = lane & 3;    // slice within quad
    const int q    = lane >> 2;   // token within octet

    sW[tid * 2 + 0] = w[tid * 2 + 0];
    sW[tid * 2 + 1] = w[tid * 2 + 1];
    __syncthreads();

    // W packed by e-pairs in butterfly arrival order:
    //   slot s holds e-block b = i ^ s; h selects pair {4b+2h, 4b+2h+1};
    //   Wc[s][h][r] = { W[4i+r][4b+2h], W[4i+r][4b+2h+1] }
    unsigned long long Wc[4][2][4];
#pragma unroll
    for (int s = 0; s < 4; s++) {
        const int b = i ^ s;
#pragma unroll
        for (int h = 0; h < 2; h++) {
            const int e0 = 4 * b + 2 * h;
#pragma unroll
            for (int r = 0; r < 4; r++)
                Wc[s][h][r] = pack2(sW[(4 * i + r) * 16 + e0],
                                    sW[(4 * i + r) * 16 + e0 + 1]);
        }
    }
    const float4 th = reinterpret_cast<const float4*>(theta)[i];

    const int nblk = gridDim.x;
    const int bid  = blockIdx.x;
    const int ngrp = ntok / GT;         // full 64-token groups

    // ---- prefill: issue S-1 stages ----
    int gp = bid;
#pragma unroll
    for (int s = 0; s < S - 1; s++) {
        if (gp < ngrp) {
            const float4* src = x4 + (size_t)gp * GF4;
            cp16(&sx[s][tid],       src + tid);
            cp16(&sx[s][tid + 128], src + tid + 128);
        }
        cp_commit();
        gp += nblk;
    }

    int it = 0;
    for (int g = bid; g < ngrp; g += nblk, it++) {
        cp_wait<S - 2>();           // stage (it % S) has landed
        __syncthreads();            // everyone past consume of stage (it-1)%S

        // issue next stage into the slot freed last iteration
        {
            const int ws = (it + S - 1) % S;
            if (gp < ngrp) {
                const float4* src = x4 + (size_t)gp * GF4;
                cp16(&sx[ws][tid],       src + tid);
                cp16(&sx[ws][tid + 128], src + tid + 128);
            }
            cp_commit();
            gp += nblk;
        }

        // consume current stage: each warp processes octets 2*wid, 2*wid+1
        const int cs = it % S;
        float4* dst = out4 + (size_t)g * GF4;
#pragma unroll
        for (int k = 0; k < 2; k++) {
            const int oct = wid * 2 + k;
            const float4 xv = sx[cs][oct * 32 + lane];
            const float4 yv = compute_octet(xv, th, Wc);
            __stcs(dst + oct * 32 + lane, yv);
        }
    }

    // ---- generic tail (ntok % GT tokens) — never runs for this shape ----
    const int tstart = ngrp * GT;
    if (bid == 0 && tstart < ntok) {
        const int toct0 = tstart >> 3;
        const int ntail_oct = (ntok - tstart + 7) >> 3;
        for (int oct = wid; oct < ntail_oct; oct += BLK / 32) {
            const int tok = tstart + oct * 8 + q;
            float4 xv = (tok < ntok)
                          ? __ldcs(&x4[(size_t)(toct0 + oct) * 32 + lane])
                          : make_float4(0.f, 0.f, 0.f, 0.f);
            const float4 yv = compute_octet(xv, th, Wc);
            if (tok < ntok)
                __stcs(&out4[(size_t)(toct0 + oct) * 32 + lane], yv);
        }
    }
}

extern "C" void kernel_launch(void* const* d_in, const int* in_sizes, int n_in,
                              void* d_out, int out_size) {
    const float* x     = (const float*)d_in[0];   // [B, S, 16] f32
    const float* theta = (const float*)d_in[1];   // [16] f32
    const float* w     = (const float*)d_in[2];   // [16, 16] f32
    float* out         = (float*)d_out;           // [B, S, 16] f32

    const int ntok = in_sizes[0] / 16;

    const int ngrp = ntok / GT;
    int blocks = 148 * 4;                  // single wave, 4 blocks/SM
    if (blocks > ngrp && ngrp > 0) blocks = ngrp;
    if (blocks < 1) blocks = 1;

    qmha_kernel<<<blocks, BLK>>>((const float4*)x, theta, w, (float4*)out, ntok);
}

// round 14
// speedup vs baseline: 1.0833x; 1.0156x over previous
#include <cuda_runtime.h>

// y[tok][o] = sum_e cos(x[tok][e] + theta[e]) * W[o][e],  E = 16, ntok = 1,048,576
//
// cp.async 4-stage smem ring, 128 tokens (8KB) per stage; 4 cp.async.cg 16B
// per thread per stage; wait_group<2> + one __syncthreads per stage (per 4
// octets/warp). Compute: warp handles 8-token octets (quad q owns token q,
// lane-slice i owns components/outputs [4i..4i+4)); W in registers
// (butterfly-permuted); z exchanged as packed f32x2 via shfl.xor.
// launch_bounds(128,5): 20 warps/SM, smem-funded pipeline.

#define BLK 128
#define S   4       // pipeline stages
#define GT  128     // tokens per stage
#define GF4 (GT * 4)    // float4 per stage (512) = 8KB
#define OPS (GT / 8)    // octets per stage (16)

__device__ __forceinline__ unsigned long long pack2(float a, float b) {
    unsigned long long r;
    asm("mov.b64 %0, {%1, %2};" : "=l"(r) : "f"(a), "f"(b));
    return r;
}
__device__ __forceinline__ void unpack2(unsigned long long v, float& a, float& b) {
    asm("mov.b64 {%0, %1}, %2;" : "=f"(a), "=f"(b) : "l"(v));
}
__device__ __forceinline__ unsigned long long ffma2(unsigned long long a,
                                                    unsigned long long b,
                                                    unsigned long long c) {
    unsigned long long d;
    asm("fma.rn.f32x2 %0, %1, %2, %3;" : "=l"(d) : "l"(a), "l"(b), "l"(c));
    return d;
}
__device__ __forceinline__ unsigned long long fmul2(unsigned long long a,
                                                    unsigned long long b) {
    unsigned long long d;
    asm("mul.rn.f32x2 %0, %1, %2;" : "=l"(d) : "l"(a), "l"(b));
    return d;
}
__device__ __forceinline__ unsigned long long shflx64(unsigned long long v, int m) {
    return __shfl_xor_sync(0xFFFFFFFFu, v, m, 4);
}
__device__ __forceinline__ void cp16(float4* dst_smem, const float4* src) {
    unsigned int d = (unsigned int)__cvta_generic_to_shared(dst_smem);
    asm volatile("cp.async.cg.shared.global [%0], [%1], 16;"
                 :: "r"(d), "l"(src) : "memory");
}
__device__ __forceinline__ void cp_commit() {
    asm volatile("cp.async.commit_group;" ::: "memory");
}
template <int N>
__device__ __forceinline__ void cp_wait() {
    asm volatile("cp.async.wait_group %0;" :: "n"(N) : "memory");
}

// one 8-token octet: xv is this lane's float4 slice; returns this lane's y slice
__device__ __forceinline__ float4 compute_octet(
    float4 xv, float4 th, const unsigned long long (&Wc)[4][2][4])
{
    const unsigned long long p0 = pack2(__cosf(xv.x + th.x), __cosf(xv.y + th.y));
    const unsigned long long p1 = pack2(__cosf(xv.z + th.z), __cosf(xv.w + th.w));

    const unsigned long long q0 = shflx64(p0, 1);
    const unsigned long long q1 = shflx64(p1, 1);

    unsigned long long acc[4];
#pragma unroll
    for (int r = 0; r < 4; r++) {
        acc[r] = fmul2(p0, Wc[0][0][r]);
        acc[r] = ffma2(p1, Wc[0][1][r], acc[r]);
    }
    const unsigned long long r0 = shflx64(p0, 2);
    const unsigned long long r1 = shflx64(p1, 2);
#pragma unroll
    for (int r = 0; r < 4; r++) {
        acc[r] = ffma2(q0, Wc[1][0][r], acc[r]);
        acc[r] = ffma2(q1, Wc[1][1][r], acc[r]);
    }
    const unsigned long long s0 = shflx64(q0, 2);
    const unsigned long long s1 = shflx64(q1, 2);
#pragma unroll
    for (int r = 0; r < 4; r++) {
        acc[r] = ffma2(r0, Wc[2][0][r], acc[r]);
        acc[r] = ffma2(r1, Wc[2][1][r], acc[r]);
    }
#pragma unroll
    for (int r = 0; r < 4; r++) {
        acc[r] = ffma2(s0, Wc[3][0][r], acc[r]);
        acc[r] = ffma2(s1, Wc[3][1][r], acc[r]);
    }

    float4 yv;
    float a, b;
    unpack2(acc[0], a, b); yv.x = a + b;
    unpack2(acc[1], a, b); yv.y = a + b;
    unpack2(acc[2], a, b); yv.z = a + b;
    unpack2(acc[3], a, b); yv.w = a + b;
    return yv;
}

__global__ __launch_bounds__(BLK, 5)
void qmha_kernel(const float4* __restrict__ x4,
                 const float* __restrict__ theta,
                 const float* __restrict__ w,      // [16][16] row-major w[o][e]
                 float4* __restrict__ out4,
                 int ntok)
{
    __shared__ float sW[256];
    __shared__ __align__(16) float4 sx[S][GF4];   // 32KB ring

    const int tid  = threadIdx.x;
    const int lane = tid & 31;
    const int wid  = tid >> 5;
    const int i    = lane & 3;    // slice within quad
    const int q    = lane >> 2;   // token within octet

    sW[tid * 2 + 0] = w[tid * 2 + 0];
    sW[tid * 2 + 1] = w[tid * 2 + 1];
    __syncthreads();

    // W packed by e-pairs in butterfly arrival order:
    //   slot s holds e-block b = i ^ s; h selects pair {4b+2h, 4b+2h+1};
    //   Wc[s][h][r] = { W[4i+r][4b+2h], W[4i+r][4b+2h+1] }
    unsigned long long Wc[4][2][4];
#pragma unroll
    for (int s = 0; s < 4; s++) {
        const int b = i ^ s;
#pragma unroll
        for (int h = 0; h < 2; h++) {
            const int e0 = 4 * b + 2 * h;
#pragma unroll
            for (int r = 0; r < 4; r++)
                Wc[s][h][r] = pack2(sW[(4 * i + r) * 16 + e0],
                                    sW[(4 * i + r) * 16 + e0 + 1]);
        }
    }
    const float4 th = reinterpret_cast<const float4*>(theta)[i];

    const int nblk = gridDim.x;
    const int bid  = blockIdx.x;
    const int ngrp = ntok / GT;         // full 128-token groups

    // ---- prefill: issue S-1 stages ----
    int gp = bid;
#pragma unroll
    for (int s = 0; s < S - 1; s++) {
        if (gp < ngrp) {
            const float4* src = x4 + (size_t)gp * GF4;
#pragma unroll
            for (int c = 0; c < GF4 / BLK; c++)
                cp16(&sx[s][tid + c * BLK], src + tid + c * BLK);
        }
        cp_commit();
        gp += nblk;
    }

    int it = 0;
    for (int g = bid; g < ngrp; g += nblk, it++) {
        cp_wait<S - 2>();           // stage (it % S) has landed
        __syncthreads();            // everyone past consume of stage (it-1)%S

        // issue next stage into the slot freed last iteration
        {
            const int ws = (it + S - 1) % S;
            if (gp < ngrp) {
                const float4* src = x4 + (size_t)gp * GF4;
#pragma unroll
                for (int c = 0; c < GF4 / BLK; c++)
                    cp16(&sx[ws][tid + c * BLK], src + tid + c * BLK);
            }
            cp_commit();
            gp += nblk;
        }

        // consume current stage: each warp processes 4 octets (wid + 4k)
        const int cs = it % S;
        float4* dst = out4 + (size_t)g * GF4;
#pragma unroll
        for (int k = 0; k < OPS / 4; k++) {
            const int oct = wid + 4 * k;
            const float4 xv = sx[cs][oct * 32 + lane];
            const float4 yv = compute_octet(xv, th, Wc);
            __stcs(dst + oct * 32 + lane, yv);
        }
    }

    // ---- generic tail (ntok % GT tokens) — never runs for this shape ----
    const int tstart = ngrp * GT;
    if (bid == 0 && tstart < ntok) {
        const int toct0 = tstart >> 3;
        const int ntail_oct = (ntok - tstart + 7) >> 3;
        for (int oct = wid; oct < ntail_oct; oct += BLK / 32) {
            const int tok = tstart + oct * 8 + q;
            float4 xv = (tok < ntok)
                          ? __ldcs(&x4[(size_t)(toct0 + oct) * 32 + lane])
                          : make_float4(0.f, 0.f, 0.f, 0.f);
            const float4 yv = compute_octet(xv, th, Wc);
            if (tok < ntok)
                __stcs(&out4[(size_t)(toct0 + oct) * 32 + lane], yv);
        }
    }
}

extern "C" void kernel_launch(void* const* d_in, const int* in_sizes, int n_in,
                              void* d_out, int out_size) {
    const float* x     = (const float*)d_in[0];   // [B, S, 16] f32
    const float* theta = (const float*)d_in[1];   // [16] f32
    const float* w     = (const float*)d_in[2];   // [16, 16] f32
    float* out         = (float*)d_out;           // [B, S, 16] f32

    const int ntok = in_sizes[0] / 16;

    const int ngrp = ntok / GT;
    int blocks = 148 * 5;                  // single wave target, 5 blocks/SM
    if (blocks > ngrp && ngrp > 0) blocks = ngrp;
    if (blocks < 1) blocks = 1;

    qmha_kernel<<<blocks, BLK>>>((const float4*)x, theta, w, (float4*)out, ntok);
}